// round 8
// baseline (speedup 1.0000x reference)
#include <cuda_runtime.h>
#include <cstdint>
#include <math.h>

#define NN     4096
#define HDIM   256
#define HEADS  4
#define HD     64
#define EC     131072
#define TOPK   15
#define CAP    160
#define RT     512
#define CPT    8
#define BUFSZ  256
#define GRID   296      // 2 blocks per SM (148 SMs), one wave
#define FULLM  0xffffffffu

// ---------------- device scratch ----------------
__device__ float2 g_vd[HEADS][HDIM];
__device__ float2 g_vs[HEADS][HDIM];
__device__ float4 g_sd[NN];
__device__ float4 g_ss[NN];
__device__ float  g_badj[NN];            // act_j ? 0.15*sum(ss_j) : -inf
__device__ int    g_cur[NN];
__device__ ulonglong2 g_edge[NN * CAP];  // .x = (pos<<32)|float_bits(w), .y = col
__device__ int    g_is_byte;

// ---------------- dynamic smem layout for k_row ----------------
struct RowSmem {
    float4 ss[NN];                 // 64 KB  operand cache
    unsigned long long buf[BUFSZ]; // 2 KB   candidate buffer
    unsigned long long sel[TOPK];
    float  badj[NN];               // 16 KB
    float  corr[NN];               // 16 KB  resolved corr weights (0 when absent)
    float  ewt[CAP];
    float  ex[TOPK];
    int    hist1[256];
    int    hist2[256];
    int    ecol[CAP];
    int    epos[CAP];
    int    cnt, B1, above1, B2, above2;
};

// ---------------- double-single helpers ----------------
__device__ __forceinline__ void dsadd(float& s, float& c, float p, float pe) {
    float t = s + p;
    float z = t - s;
    float e = (s - (t - z)) + (p - z);
    s = t;
    c += e + pe;
}

// ---------------- L1: detect bool width + zero counters + fold ----------------
__global__ __launch_bounds__(256) void k_setup(const unsigned* __restrict__ mask_words,
                                               const float* __restrict__ W,
                                               const float* __restrict__ att) {
    int b = blockIdx.x, tid = threadIdx.x;
    if (b == 0) {
        __shared__ int s_byte;
        if (tid == 0) s_byte = 0;
        __syncthreads();
        for (int t = tid; t < 4096; t += 256) {
            unsigned w = mask_words[t];
            if (w > 1u) {
                unsigned b0 = w & 0xFF, b1 = (w >> 8) & 0xFF,
                         b2 = (w >> 16) & 0xFF, b3 = w >> 24;
                if (b0 <= 1u && b1 <= 1u && b2 <= 1u && b3 <= 1u) s_byte = 1;
            }
        }
        __syncthreads();
        if (tid == 0) g_is_byte = s_byte;
    } else if (b <= 16) {
        g_cur[(b - 1) * 256 + tid] = 0;
    } else {
        int h = b - 17;
        int k = tid;
        float sd = 0.f, cd = 0.f, ss = 0.f, cs = 0.f;
        #pragma unroll 8
        for (int dd = 0; dd < HD; dd++) {
            float w   = W[(h * HD + dd) * HDIM + k];
            float ad  = att[h * 2 * HD + dd];
            float as_ = att[h * 2 * HD + HD + dd];
            float p = ad * w;  float pe = fmaf(ad, w, -p);
            dsadd(sd, cd, p, pe);
            p = as_ * w;       pe = fmaf(as_, w, -p);
            dsadd(ss, cs, p, pe);
        }
        float hi = sd + cd;
        g_vd[h][k] = make_float2(hi, (sd - hi) + cd);
        hi = ss + cs;
        g_vs[h][k] = make_float2(hi, (ss - hi) + cs);
    }
}

// ---------------- L2: sds + edge scatter ----------------
__global__ __launch_bounds__(1024) void k_mid(const float* __restrict__ E,
                                              const int* __restrict__ eidx,
                                              const float* __restrict__ ew,
                                              const uint8_t* __restrict__ act) {
    int b = blockIdx.x;
    if (b < 128) {
        int wid = threadIdx.x >> 5;
        int lane = threadIdx.x & 31;
        int g = b * 32 + wid;
        const float* er = E + (size_t)g * HDIM;
        float s[8], c[8];
        #pragma unroll
        for (int a = 0; a < 8; a++) { s[a] = 0.f; c[a] = 0.f; }
        for (int k = lane; k < HDIM; k += 32) {
            float e = er[k];
            #pragma unroll
            for (int h = 0; h < HEADS; h++) {
                float2 v = g_vd[h][k];
                float p = e * v.x;
                float pe = fmaf(e, v.x, -p);
                pe = fmaf(e, v.y, pe);
                dsadd(s[h], c[h], p, pe);
                v = g_vs[h][k];
                p = e * v.x;
                pe = fmaf(e, v.x, -p);
                pe = fmaf(e, v.y, pe);
                dsadd(s[4 + h], c[4 + h], p, pe);
            }
        }
        #pragma unroll
        for (int off = 16; off; off >>= 1) {
            #pragma unroll
            for (int a = 0; a < 8; a++) {
                float os = __shfl_down_sync(FULLM, s[a], off);
                float oc = __shfl_down_sync(FULLM, c[a], off);
                float t = s[a] + os;
                float z = t - s[a];
                c[a] += oc + ((s[a] - (t - z)) + (os - z));
                s[a] = t;
            }
        }
        if (lane == 0) {
            g_sd[g] = make_float4(s[0] + c[0], s[1] + c[1], s[2] + c[2], s[3] + c[3]);
            float t0 = s[4] + c[4], t1 = s[5] + c[5], t2 = s[6] + c[6], t3 = s[7] + c[7];
            g_ss[g] = make_float4(t0, t1, t2, t3);
            bool aj = g_is_byte ? (act[g] != 0) : (((const unsigned*)act)[g] != 0u);
            g_badj[g] = aj ? 0.15f * ((t0 + t1) + (t2 + t3)) : -INFINITY;
        }
    } else {
        int e = (b - 128) * 1024 + threadIdx.x;
        if (e < EC) {
            int r = eidx[e];
            int cc = eidx[EC + e];
            int p = atomicAdd(&g_cur[r], 1);
            if (p < CAP) {
                ulonglong2 rec;
                rec.x = ((unsigned long long)(unsigned)e << 32) |
                        (unsigned long long)__float_as_uint(ew[e]);
                rec.y = (unsigned long long)(unsigned)cc;
                g_edge[r * CAP + p] = rec;
            }
        }
    }
}

// warp0-only: largest bin B with suffix-count(B) >= K; outAbove = count in bins > B
__device__ __forceinline__ void scan_hist(const int* __restrict__ hist, int K,
                                          int* outB, int* outAbove) {
    int lane = threadIdx.x & 31;
    int base = lane * 8;
    int h[8];
    #pragma unroll
    for (int r = 0; r < 8; r++) h[r] = hist[base + r];
    int ls[8];
    int s = 0;
    #pragma unroll
    for (int r = 7; r >= 0; r--) { s += h[r]; ls[r] = s; }
    int run = s;
    #pragma unroll
    for (int off = 1; off < 32; off <<= 1) {
        int t = __shfl_down_sync(FULLM, run, off);
        if (lane + off < 32) run += t;
    }
    int above = run - s;
    int cand = -1, candAbove = 0;
    #pragma unroll
    for (int r = 7; r >= 0; r--) {
        if (cand < 0 && above + ls[r] >= K) {
            cand = base + r;
            candAbove = above + ls[r] - h[r];
        }
    }
    int bestB = cand, bestA = candAbove;
    #pragma unroll
    for (int off = 16; off; off >>= 1) {
        int ob = __shfl_xor_sync(FULLM, bestB, off);
        int oa = __shfl_xor_sync(FULLM, bestA, off);
        if (ob > bestB) { bestB = ob; bestA = oa; }
    }
    if (lane == 0) {
        *outB = (bestB < 0) ? 0 : bestB;
        *outAbove = (bestB < 0) ? 0 : bestA;
    }
}

// ---------------- L3: persistent blocks, smem operand cache ----------------
__global__ __launch_bounds__(RT) void k_row(const uint8_t* __restrict__ mask,
                                            const uint8_t* __restrict__ act,
                                            const float* __restrict__ lambda_p,
                                            float* __restrict__ out) {
    extern __shared__ RowSmem sm[];
    RowSmem* S = sm;

    const int tid = threadIdx.x;
    const int lane = tid & 31;
    const int wid = tid >> 5;

    // ---- block prologue: fill operand caches, zero corr ----
    #pragma unroll
    for (int k = 0; k < CPT; k++) {
        int j = tid + k * RT;
        S->ss[j] = __ldg(&g_ss[j]);
        S->badj[j] = __ldg(&g_badj[j]);
        S->corr[j] = 0.f;
    }
    const float lam = __ldg(lambda_p);
    const int is_byte = g_is_byte;
    __syncthreads();

    for (int i = blockIdx.x; i < NN; i += GRID) {
        // ---- per-row init + edge load ----
        if (tid < 256) { S->hist1[tid] = 0; S->hist2[tid] = 0; }
        if (tid == RT - 1) S->cnt = 0;
        if (tid >= 256 && tid < 256 + TOPK) S->sel[tid - 256] = 0ULL;
        int cnt = g_cur[i];
        if (cnt > CAP) cnt = CAP;
        if (tid < cnt) {
            ulonglong2 rec = __ldg(&g_edge[i * CAP + tid]);
            S->ecol[tid] = (int)rec.y;
            S->epos[tid] = (int)(rec.x >> 32);
            S->ewt[tid]  = __uint_as_float((unsigned)rec.x);
        }
        __syncthreads();

        // ---- resolve last-write-wins + scatter winners (no atomics) ----
        if (tid < cnt) {
            int c = S->ecol[tid], p = S->epos[tid];
            bool win = true;
            for (int s = 0; s < cnt; s++)
                if (S->ecol[s] == c && S->epos[s] > p) win = false;
            if (win) S->corr[c] = S->ewt[tid];
        }
        __syncthreads();

        // ---- compute 8 keys + level-1 histogram ----
        const float4 sdi = __ldg(&g_sd[i]);
        const float ci = 0.15f * ((sdi.x + sdi.y) + (sdi.z + sdi.w));
        const uint8_t*  mrow8  = mask + (size_t)i * NN;
        const unsigned* mrow32 = (const unsigned*)mask + (size_t)i * NN;
        const bool acti = is_byte ? (act[i] != 0) : (((const unsigned*)act)[i] != 0u);

        unsigned kk[CPT];
        #pragma unroll
        for (int k = 0; k < CPT; k++) {
            int j = tid + k * RT;
            float4 ssj = S->ss[j];
            float x0 = sdi.x + ssj.x;
            float x1 = sdi.y + ssj.y;
            float x2 = sdi.z + ssj.z;
            float x3 = sdi.w + ssj.w;
            float sa = fabsf(x0) + fabsf(x1);
            float sb = fabsf(x2) + fabsf(x3);
            float w = S->corr[j];
            float a = S->badj[j];
            bool mj = is_byte ? (mrow8[j] != 0) : (mrow32[j] != 0u);
            float sc = ci + fmaf(lam, w, a);
            sc = fmaf(0.1f, sa + sb, sc);
            sc = (acti && mj) ? sc : -INFINITY;
            unsigned u = __float_as_uint(sc);
            u ^= ((unsigned)(((int)u) >> 31)) | 0x80000000u;
            kk[k] = u;
        }
        #pragma unroll
        for (int k = 0; k < CPT; k++) {
            unsigned b1 = kk[k] >> 24;
            unsigned peers = __match_any_sync(FULLM, b1);
            if ((peers & ((1u << lane) - 1u)) == 0)
                atomicAdd(&S->hist1[b1], (int)__popc(peers));
        }
        __syncthreads();

        // ---- scan1 (warp0) + corr un-scatter (parallel) ----
        if (wid == 0) scan_hist(S->hist1, TOPK, &S->B1, &S->above1);
        if (tid < cnt) S->corr[S->ecol[tid]] = 0.f;
        __syncthreads();
        const int B1 = S->B1;
        const int above1 = S->above1;

        // ---- level-2 histogram within bin B1 ----
        #pragma unroll
        for (int k = 0; k < CPT; k++) {
            if ((int)(kk[k] >> 24) == B1)
                atomicAdd(&S->hist2[(kk[k] >> 16) & 0xFF], 1);
        }
        __syncthreads();
        if (wid == 0) scan_hist(S->hist2, TOPK - above1, &S->B2, &S->above2);
        __syncthreads();
        const int B2 = S->B2;

        // ---- append candidates ----
        #pragma unroll
        for (int k = 0; k < CPT; k++) {
            int b1k = (int)(kk[k] >> 24);
            bool cand = (b1k > B1) || (b1k == B1 && (int)((kk[k] >> 16) & 0xFF) >= B2);
            if (cand) {
                int p = atomicAdd(&S->cnt, 1);
                if (p < BUFSZ) {
                    int j = tid + k * RT;
                    S->buf[p] = ((unsigned long long)kk[k] << 32) |
                                (unsigned long long)(0xFFFFFFFFu - (unsigned)j);
                }
            }
        }
        __syncthreads();

        // ---- rank-select top-15 ----
        int n = S->cnt < BUFSZ ? S->cnt : BUFSZ;
        if (tid < BUFSZ) {
            unsigned long long K = (tid < n) ? S->buf[tid] : 0ULL;
            int rank = 0;
            for (int s = 0; s < n; s++) rank += (S->buf[s] > K);
            if (tid < n && rank < TOPK) S->sel[rank] = K;
        }
        __syncthreads();

        // ---- decode + softmax + write ----
        if (tid < TOPK) {
            unsigned long long k64 = S->sel[tid];
            unsigned u = (unsigned)(k64 >> 32);
            float v = (u & 0x80000000u) ? __uint_as_float(u ^ 0x80000000u)
                                        : __uint_as_float(~u);
            unsigned j = 0xFFFFFFFFu - (unsigned)(k64 & 0xFFFFFFFFu);

            unsigned u0 = (unsigned)(S->sel[0] >> 32);
            float v0 = (u0 & 0x80000000u) ? __uint_as_float(u0 ^ 0x80000000u)
                                          : __uint_as_float(~u0);
            S->ex[tid] = expf(v - v0);

            out[(size_t)i * TOPK + tid] = (float)j;
            out[(size_t)NN * TOPK + (size_t)i * TOPK + tid] = (float)i;
        }
        __syncthreads();
        if (tid < TOPK) {
            float sum = 0.f;
            #pragma unroll
            for (int r = 0; r < TOPK; r++) sum += S->ex[r];
            out[2 * (size_t)NN * TOPK + (size_t)i * TOPK + tid] = S->ex[tid] / sum;
        }
        __syncthreads();   // sel/ex/hist reused next row
    }
}

// ---------------- launcher ----------------
extern "C" void kernel_launch(void* const* d_in, const int* in_sizes, int n_in,
                              void* d_out, int out_size) {
    const float*   emb  = (const float*)d_in[0];
    const float*   W    = (const float*)d_in[1];
    const float*   att  = (const float*)d_in[2];
    const float*   lam  = (const float*)d_in[3];
    const uint8_t* mask = (const uint8_t*)d_in[4];
    const uint8_t* act  = (const uint8_t*)d_in[5];
    const int*     eidx = (const int*)d_in[6];
    const float*   ew   = (const float*)d_in[7];
    float* out = (float*)d_out;

    cudaFuncSetAttribute(k_row, cudaFuncAttributeMaxDynamicSharedMemorySize,
                         (int)sizeof(RowSmem));

    k_setup<<<21, 256>>>((const unsigned*)mask, W, att);
    k_mid<<<256, 1024>>>(emb, eidx, ew, act);
    k_row<<<GRID, RT, sizeof(RowSmem)>>>(mask, act, lam, out);
}